// round 2
// baseline (speedup 1.0000x reference)
#include <cuda_runtime.h>
#include <math.h>
#include <stdint.h>

// LSTM: T=1024, B=64, I=256, H=512, O=5
// out = [outputs (T*B*O) | h_T (B*H) | c_T (B*H)]  (pytree flatten order)

#define TT 1024
#define BB 64
#define II 256
#define HH 512
#define G4 2048
#define OO 5

#define REC_CTAS 128

// ---- device scratch (static __device__ globals: the sanctioned no-alloc path) ----
__device__ float g_xgT[(size_t)TT * G4 * BB];   // [T][4H][B]  pre-gates, 512MB
__device__ float g_hsT[(size_t)TT * HH * BB];   // [T][H][B]   h history, 128MB
__device__ float g_hT[2][HH * BB];              // ping-pong h, [512][64]
__device__ unsigned g_bar_count;
__device__ volatile unsigned g_bar_gen;

__device__ __forceinline__ float sigf(float x) {
    return 1.0f / (1.0f + __expf(-x));
}

// Hand-rolled grid barrier. Safe: all REC_CTAS CTAs are co-resident
// (128 CTAs <= 148 SMs, 1 CTA/SM at this smem/reg footprint).
// Self-resetting (count returns to 0 every barrier) -> graph-replay safe.
__device__ __forceinline__ void grid_sync() {
    __syncthreads();
    if (threadIdx.x == 0) {
        unsigned old = g_bar_gen;
        __threadfence();
        unsigned t = atomicAdd(&g_bar_count, 1u);
        if (t == REC_CTAS - 1) {
            atomicExch(&g_bar_count, 0u);
            __threadfence();
            g_bar_gen = old + 1u;
        } else {
            while (g_bar_gen == old) { }
            __threadfence();
        }
    }
    __syncthreads();
}

// ============================================================================
// Kernel 1: xg[t][n][b] = sum_k x[t][b][k] * W_ih[n][k] + b_ih[n] + b_hh[n]
// Tiled SGEMM: M-tile = 64 (one t), N-tile = 64, BK = 16, 256 threads, 4x4/thread.
// Output written TRANSPOSED per t ([4H][B]) so the recurrence reads coalesce.
// ============================================================================
__global__ void __launch_bounds__(256) pregemm_kernel(
    const float* __restrict__ x, const float* __restrict__ Wih,
    const float* __restrict__ bih, const float* __restrict__ bhh)
{
    __shared__ float As[16][68];   // [k][b]
    __shared__ float Bs[16][68];   // [k][n_local]
    const int t   = blockIdx.x >> 5;
    const int n0  = (blockIdx.x & 31) << 6;
    const int tid = threadIdx.x;
    const int lrow = tid >> 2;          // 0..63
    const int kk4  = (tid & 3) << 2;    // 0,4,8,12
    const int tx = tid & 15;            // n sub-tile
    const int ty = tid >> 4;            // b sub-tile

    const float* Ap = x   + (size_t)(t * BB) * II;
    const float* Bp = Wih + (size_t)n0 * II;

    float acc[4][4];
    #pragma unroll
    for (int i = 0; i < 4; i++)
        #pragma unroll
        for (int j = 0; j < 4; j++) acc[i][j] = 0.0f;

    for (int kc = 0; kc < II; kc += 16) {
        float4 a = *(const float4*)(Ap + (size_t)lrow * II + kc + kk4);
        float4 b = *(const float4*)(Bp + (size_t)lrow * II + kc + kk4);
        As[kk4+0][lrow] = a.x; As[kk4+1][lrow] = a.y;
        As[kk4+2][lrow] = a.z; As[kk4+3][lrow] = a.w;
        Bs[kk4+0][lrow] = b.x; Bs[kk4+1][lrow] = b.y;
        Bs[kk4+2][lrow] = b.z; Bs[kk4+3][lrow] = b.w;
        __syncthreads();
        #pragma unroll
        for (int kk = 0; kk < 16; kk++) {
            float4 av4 = *(const float4*)&As[kk][ty * 4];
            float4 bv4 = *(const float4*)&Bs[kk][tx * 4];
            float av[4] = {av4.x, av4.y, av4.z, av4.w};
            float bv[4] = {bv4.x, bv4.y, bv4.z, bv4.w};
            #pragma unroll
            for (int i = 0; i < 4; i++)
                #pragma unroll
                for (int jj = 0; jj < 4; jj++)
                    acc[i][jj] = fmaf(av[i], bv[jj], acc[i][jj]);
        }
        __syncthreads();
    }

    float* outp = g_xgT + (size_t)t * (G4 * BB);
    #pragma unroll
    for (int jj = 0; jj < 4; jj++) {
        int n = n0 + tx * 4 + jj;
        float bias = bih[n] + bhh[n];
        float4 v = make_float4(acc[0][jj] + bias, acc[1][jj] + bias,
                               acc[2][jj] + bias, acc[3][jj] + bias);
        *(float4*)(outp + (size_t)n * BB + ty * 4) = v;
    }
}

// ============================================================================
// Kernel 2: persistent LSTM recurrence. 128 CTAs x 256 threads.
// CTA j owns hidden units [4j, 4j+4) -> 16 gate rows {i,f,g,o} x 4 units.
// W_hh slice (16x512) + cell state live in SMEM across all 1024 steps.
// Per step: 64x16 GEMM slice vs full h (K=512), nonlinearity, h broadcast,
// grid barrier.
// ============================================================================
__global__ void __launch_bounds__(256, 1) lstm_rec_kernel(
    const float* __restrict__ Whh, float* __restrict__ d_out, int out_size)
{
    __shared__ float wsm[16][516];   // padded: 516 % 32 = 4 -> no LDS conflict
    __shared__ float gsm[16][64];    // gate pre-activations for this step
    __shared__ float csm[4][64];     // cell state (persistent across steps)

    const int j   = blockIdx.x;
    const int tid = threadIdx.x;
    const int bq  = tid & 15;        // batch quad: b = 4*bq .. 4*bq+3
    const int rid = tid >> 4;        // 0..15: local gate row
    const int gate = rid >> 2;
    const int u    = rid & 3;
    const int grow = gate * HH + j * 4 + u;   // global gate row in [0,2048)

    // Load W_hh rows for this CTA (coalesced over k)
    for (int s = tid; s < 16 * HH; s += 256) {
        int r = s >> 9;
        int k = s & (HH - 1);
        int rr = (r >> 2) * HH + j * 4 + (r & 3);
        wsm[r][k] = Whh[(size_t)rr * HH + k];
    }
    // Zero cell state and this CTA's slice of h0 (per-replay reset)
    {
        int uu = tid >> 6, b = tid & 63;
        csm[uu][b] = 0.0f;
        g_hT[0][(j * 4 + uu) * BB + b] = 0.0f;
    }
    __threadfence();
    grid_sync();

    int cur = 0;
    for (int step = 0; step < TT; step++) {
        // init accumulators from precomputed x-gates (already include biases)
        const float* xgp = g_xgT + (size_t)step * (G4 * BB)
                                 + (size_t)grow * BB + bq * 4;
        float4 acc = *(const float4*)xgp;

        // gates[b, grow] += sum_k h[k][b] * W_hh[grow][k]
        const float4* hp = (const float4*)(g_hT[cur]) + bq;  // + k*16 per step
        #pragma unroll 8
        for (int k = 0; k < HH; k++) {
            float4 hv = __ldcg(hp + k * 16);   // L2 (h written by other SMs)
            float w = wsm[rid][k];
            acc.x = fmaf(hv.x, w, acc.x);
            acc.y = fmaf(hv.y, w, acc.y);
            acc.z = fmaf(hv.z, w, acc.z);
            acc.w = fmaf(hv.w, w, acc.w);
        }
        gsm[rid][bq * 4 + 0] = acc.x;
        gsm[rid][bq * 4 + 1] = acc.y;
        gsm[rid][bq * 4 + 2] = acc.z;
        gsm[rid][bq * 4 + 3] = acc.w;
        __syncthreads();

        // elementwise LSTM cell: thread -> (unit uu, batch b)
        {
            int uu = tid >> 6, b = tid & 63;
            float ig = sigf(gsm[uu][b]);
            float fg = sigf(gsm[4 + uu][b]);
            float gg = tanhf(gsm[8 + uu][b]);
            float og = sigf(gsm[12 + uu][b]);
            float c  = fmaf(fg, csm[uu][b], ig * gg);
            float h  = og * tanhf(c);
            csm[uu][b] = c;
            int gu = j * 4 + uu;
            g_hT[cur ^ 1][gu * BB + b] = h;                          // broadcast
            g_hsT[(size_t)step * (HH * BB) + gu * BB + b] = h;       // history
            if (step == TT - 1 && out_size >= TT * BB * OO + 2 * BB * HH) {
                d_out[TT * BB * OO + (size_t)b * HH + gu] = h;           // h_T
                d_out[TT * BB * OO + BB * HH + (size_t)b * HH + gu] = c; // c_T
            }
        }
        __threadfence();
        grid_sync();
        cur ^= 1;
    }
}

// ============================================================================
// Kernel 3: outputs[t][b][o] = sum_k hsT[t][k][b] * fc_w[o][k] + fc_b[o]
// One CTA per t; 320 threads = 5 o-groups x 64 b. Memory-bound over 128MB.
// ============================================================================
__global__ void __launch_bounds__(320) fc_kernel(
    const float* __restrict__ fcw, const float* __restrict__ fcb,
    float* __restrict__ out)
{
    __shared__ float wsm[OO][HH];
    __shared__ float bsm[OO];
    const int t   = blockIdx.x;
    const int tid = threadIdx.x;
    for (int s = tid; s < OO * HH; s += 320) wsm[s / HH][s % HH] = fcw[s];
    if (tid < OO) bsm[tid] = fcb[tid];
    __syncthreads();

    const int o = tid >> 6;   // 0..4
    const int b = tid & 63;
    const float* hp = g_hsT + (size_t)t * (HH * BB) + b;
    float acc = bsm[o];
    #pragma unroll 8
    for (int k = 0; k < HH; k++)
        acc = fmaf(hp[(size_t)k * BB], wsm[o][k], acc);
    out[(size_t)t * (BB * OO) + b * OO + o] = acc;
}

// ============================================================================
extern "C" void kernel_launch(void* const* d_in, const int* in_sizes, int n_in,
                              void* d_out, int out_size) {
    const float* x   = (const float*)d_in[0];   // [T,B,I]
    const float* Wih = (const float*)d_in[1];   // [4H,I]
    const float* Whh = (const float*)d_in[2];   // [4H,H]
    const float* bih = (const float*)d_in[3];   // [4H]
    const float* bhh = (const float*)d_in[4];   // [4H]
    const float* fcw = (const float*)d_in[5];   // [O,H]
    const float* fcb = (const float*)d_in[6];   // [O]
    float* out = (float*)d_out;

    pregemm_kernel<<<TT * 32, 256>>>(x, Wih, bih, bhh);
    lstm_rec_kernel<<<REC_CTAS, 256>>>(Whh, out, out_size);
    fc_kernel<<<TT, 320>>>(fcw, fcb, out);
}

// round 3
// speedup vs baseline: 1.3311x; 1.3311x over previous
#include <cuda_runtime.h>
#include <math.h>
#include <stdint.h>

// LSTM: T=1024, B=64, I=256, H=512, O=5
// out = [outputs (T*B*O) | h_T (B*H) | c_T (B*H)]

#define TT 1024
#define BB 64
#define II 256
#define HH 512
#define G4 2048
#define OO 5

#define REC_CTAS 128

// ---- device scratch ----
__device__ float g_xgT[(size_t)TT * G4 * BB];   // [T][4H][B]
__device__ float g_hsT[(size_t)TT * HH * BB];   // [T][H][B]
__device__ float g_hT[2][HH * BB];              // ping-pong h, [512][64]
__device__ unsigned g_bar_count;
__device__ volatile unsigned g_bar_gen;

__device__ __forceinline__ float sigf(float x) {
    return 1.0f / (1.0f + __expf(-x));
}

// Packed fp32x2 FMA (sm_100+): d = a*b + d, lanewise on 2-float packs.
#define FMA2(d, a, b) \
    asm("fma.rn.f32x2 %0, %1, %2, %0;" : "+l"(d) : "l"(a), "l"(b))

__device__ __forceinline__ void cpa16(uint32_t saddr, const void* gptr) {
    asm volatile("cp.async.cg.shared.global [%0], [%1], 16;"
                 :: "r"(saddr), "l"(gptr));
}
#define CP_COMMIT() asm volatile("cp.async.commit_group;")
#define CP_WAIT(n)  asm volatile("cp.async.wait_group %0;" :: "n"(n))

// Grid-wide barrier; all 128 CTAs co-resident (1 CTA/SM @ this smem).
__device__ __forceinline__ void grid_sync() {
    __syncthreads();
    if (threadIdx.x == 0) {
        unsigned old = g_bar_gen;
        __threadfence();
        unsigned t = atomicAdd(&g_bar_count, 1u);
        if (t == REC_CTAS - 1) {
            atomicExch(&g_bar_count, 0u);
            __threadfence();
            g_bar_gen = old + 1u;
        } else {
            while (g_bar_gen == old) { }
            __threadfence();
        }
    }
    __syncthreads();
}

// ============================================================================
// Kernel 1: xg[t][n][b] = sum_k x[t][b][k] * W_ih[n][k] + b_ih[n] + b_hh[n]
// 64(b) x 64(n) tile per CTA, BK=16, 256 threads. f32x2 packed along b.
// thread = (bx 0..15: b-quad, ny 0..15: n-quad); 2 b-pairs x 4 n per thread.
// ============================================================================
#define AS_STRIDE 68   // floats; 272B = 17*16 (float4-aligned), 4*68%32!=0
#define BS_STRIDE 66   // float2;  528B = 33*16

__global__ void __launch_bounds__(256) pregemm_kernel(
    const float* __restrict__ x, const float* __restrict__ Wih,
    const float* __restrict__ bih, const float* __restrict__ bhh)
{
    __shared__ float  As[16 * AS_STRIDE];    // [k][b]  (natural)
    __shared__ float2 Bs2[16 * BS_STRIDE];   // [k][n]  (duplicated pairs)

    const int t   = blockIdx.x >> 5;
    const int n0  = (blockIdx.x & 31) << 6;
    const int tid = threadIdx.x;
    const int lrow = tid >> 2;           // 0..63 (load row)
    const int kk4  = (tid & 3) << 2;     // 0,4,8,12
    const int bx = tid & 15;             // b-quad
    const int ny = tid >> 4;             // n-quad

    const float* Ap = x   + (size_t)(t * BB) * II;
    const float* Bp = Wih + (size_t)n0 * II;

    unsigned long long acc[2][4];        // [b-pair][n]
    #pragma unroll
    for (int i = 0; i < 2; i++)
        #pragma unroll
        for (int j = 0; j < 4; j++) acc[i][j] = 0ull;

    for (int kc = 0; kc < II; kc += 16) {
        float4 a = *(const float4*)(Ap + (size_t)lrow * II + kc + kk4);
        float4 b = *(const float4*)(Bp + (size_t)lrow * II + kc + kk4);
        As[(kk4+0)*AS_STRIDE + lrow] = a.x;
        As[(kk4+1)*AS_STRIDE + lrow] = a.y;
        As[(kk4+2)*AS_STRIDE + lrow] = a.z;
        As[(kk4+3)*AS_STRIDE + lrow] = a.w;
        Bs2[(kk4+0)*BS_STRIDE + lrow] = make_float2(b.x, b.x);
        Bs2[(kk4+1)*BS_STRIDE + lrow] = make_float2(b.y, b.y);
        Bs2[(kk4+2)*BS_STRIDE + lrow] = make_float2(b.z, b.z);
        Bs2[(kk4+3)*BS_STRIDE + lrow] = make_float2(b.w, b.w);
        __syncthreads();
        #pragma unroll
        for (int kk = 0; kk < 16; kk++) {
            ulonglong2 av = *(const ulonglong2*)&As[kk*AS_STRIDE + bx*4];
            ulonglong2 b01 = *(const ulonglong2*)&Bs2[kk*BS_STRIDE + ny*4];
            ulonglong2 b23 = *(const ulonglong2*)&Bs2[kk*BS_STRIDE + ny*4 + 2];
            FMA2(acc[0][0], av.x, b01.x); FMA2(acc[1][0], av.y, b01.x);
            FMA2(acc[0][1], av.x, b01.y); FMA2(acc[1][1], av.y, b01.y);
            FMA2(acc[0][2], av.x, b23.x); FMA2(acc[1][2], av.y, b23.x);
            FMA2(acc[0][3], av.x, b23.y); FMA2(acc[1][3], av.y, b23.y);
        }
        __syncthreads();
    }

    float* outp = g_xgT + (size_t)t * (G4 * BB);
    #pragma unroll
    for (int j = 0; j < 4; j++) {
        int n = n0 + ny * 4 + j;
        float bias = bih[n] + bhh[n];
        float2 lo = *(float2*)&acc[0][j];
        float2 hi = *(float2*)&acc[1][j];
        float4 v = make_float4(lo.x + bias, lo.y + bias,
                               hi.x + bias, hi.y + bias);
        *(float4*)(outp + (size_t)n * BB + bx * 4) = v;    // coalesced
    }
}

// ============================================================================
// Kernel 2: persistent LSTM recurrence. 128 CTAs x 256 threads, 1 CTA/SM.
// CTA j owns 16 gate rows (4 hidden units). Per step:
//   - stage h[512][64] (128KB) to SMEM via cp.async, 8 chunks, depth-2 pipe
//   - f32x2 GEMM slice from SMEM (w pre-duplicated in SMEM)
//   - nonlinearity, h broadcast, grid barrier
// ============================================================================
#define REC_SMEM_FLOATS (32768 /*hsm*/ + 16384 /*wsm2*/ + 1024 /*gsm*/ + 256 /*csm*/)
#define REC_SMEM_BYTES  (REC_SMEM_FLOATS * 4)

__global__ void __launch_bounds__(256, 1) lstm_rec_kernel(
    const float* __restrict__ Whh, float* __restrict__ d_out, int out_size)
{
    extern __shared__ float smem[];
    float*  hsm  = smem;                       // [512][64]
    float2* wsm2 = (float2*)(smem + 32768);    // [16][512] dup pairs
    float*  gsm  = smem + 32768 + 16384;       // [16][64]
    float*  csm  = gsm + 1024;                 // [4][64]

    const int j   = blockIdx.x;
    const int tid = threadIdx.x;
    const int bq  = tid & 15;
    const int rid = tid >> 4;
    const int grow = (rid >> 2) * HH + j * 4 + (rid & 3);

    const uint32_t hsm_s = (uint32_t)__cvta_generic_to_shared(hsm);

    // Load W_hh slice, duplicated into float2 pairs
    for (int s = tid; s < 16 * HH; s += 256) {
        int r = s >> 9;
        int k = s & (HH - 1);
        int rr = (r >> 2) * HH + j * 4 + (r & 3);
        float w = Whh[(size_t)rr * HH + k];
        wsm2[r * HH + k] = make_float2(w, w);
    }
    {   // reset cell state + this CTA's h0 slice (per-replay)
        int uu = tid >> 6, b = tid & 63;
        csm[uu * 64 + b] = 0.0f;
        g_hT[0][(j * 4 + uu) * BB + b] = 0.0f;
    }
    __threadfence();
    grid_sync();

    int cur = 0;
    const float2* wrow = wsm2 + rid * HH;

    for (int step = 0; step < TT; step++) {
        // acc init from precomputed x-gates (biases included)
        const float* xgp = g_xgT + ((size_t)step * G4 + grow) * BB + bq * 4;
        uint4 xv = __ldcs((const uint4*)xgp);
        unsigned long long acc01 =
            (unsigned long long)xv.x | ((unsigned long long)xv.y << 32);
        unsigned long long acc23 =
            (unsigned long long)xv.z | ((unsigned long long)xv.w << 32);

        const float* hsrc = g_hT[cur];

        // prologue: issue chunks 0 and 1 (16KB each, 4x16B per thread)
        #pragma unroll
        for (int i = 0; i < 4; i++)
            cpa16(hsm_s + (0 * 1024 + i * 256 + tid) * 16,
                  hsrc + (0 * 4096 + (i * 256 + tid) * 4));
        CP_COMMIT();
        #pragma unroll
        for (int i = 0; i < 4; i++)
            cpa16(hsm_s + (1 * 1024 + i * 256 + tid) * 16,
                  hsrc + (1 * 4096 + (i * 256 + tid) * 4));
        CP_COMMIT();

        for (int c = 0; c < 8; c++) {
            if (c < 7) CP_WAIT(1); else CP_WAIT(0);
            __syncthreads();
            if (c < 6) {   // issue chunk c+2
                int cc = c + 2;
                #pragma unroll
                for (int i = 0; i < 4; i++)
                    cpa16(hsm_s + (cc * 1024 + i * 256 + tid) * 16,
                          hsrc + (cc * 4096 + (i * 256 + tid) * 4));
                CP_COMMIT();
            }
            // compute chunk c: k in [64c, 64c+64)
            const float* hch = hsm + c * 4096 + bq * 4;
            #pragma unroll 4
            for (int kb = 0; kb < 64; kb += 4) {
                int k = c * 64 + kb;
                ulonglong2 h0 = *(const ulonglong2*)(hch + (kb + 0) * 64);
                ulonglong2 h1 = *(const ulonglong2*)(hch + (kb + 1) * 64);
                ulonglong2 h2 = *(const ulonglong2*)(hch + (kb + 2) * 64);
                ulonglong2 h3 = *(const ulonglong2*)(hch + (kb + 3) * 64);
                ulonglong2 w01 = *(const ulonglong2*)(wrow + k);
                ulonglong2 w23 = *(const ulonglong2*)(wrow + k + 2);
                FMA2(acc01, h0.x, w01.x); FMA2(acc23, h0.y, w01.x);
                FMA2(acc01, h1.x, w01.y); FMA2(acc23, h1.y, w01.y);
                FMA2(acc01, h2.x, w23.x); FMA2(acc23, h2.y, w23.x);
                FMA2(acc01, h3.x, w23.y); FMA2(acc23, h3.y, w23.y);
            }
        }

        *(float2*)&gsm[rid * 64 + bq * 4]     = *(float2*)&acc01;
        *(float2*)&gsm[rid * 64 + bq * 4 + 2] = *(float2*)&acc23;
        __syncthreads();

        {   // elementwise LSTM cell
            int uu = tid >> 6, b = tid & 63;
            float ig = sigf(gsm[uu * 64 + b]);
            float fg = sigf(gsm[(4 + uu) * 64 + b]);
            float gg = tanhf(gsm[(8 + uu) * 64 + b]);
            float og = sigf(gsm[(12 + uu) * 64 + b]);
            float c  = fmaf(fg, csm[uu * 64 + b], ig * gg);
            float h  = og * tanhf(c);
            csm[uu * 64 + b] = c;
            int gu = j * 4 + uu;
            g_hT[cur ^ 1][gu * BB + b] = h;
            __stcs(&g_hsT[(size_t)step * (HH * BB) + gu * BB + b], h);
            if (step == TT - 1 && out_size >= TT * BB * OO + 2 * BB * HH) {
                d_out[TT * BB * OO + (size_t)b * HH + gu] = h;
                d_out[TT * BB * OO + BB * HH + (size_t)b * HH + gu] = c;
            }
        }
        __threadfence();
        grid_sync();
        cur ^= 1;
    }
}

// ============================================================================
// Kernel 3: outputs[t][b][o] = sum_k hsT[t][k][b] * fc_w[o][k] + fc_b[o]
// ============================================================================
__global__ void __launch_bounds__(320) fc_kernel(
    const float* __restrict__ fcw, const float* __restrict__ fcb,
    float* __restrict__ out)
{
    __shared__ float wsm[OO][HH];
    __shared__ float bsm[OO];
    const int t   = blockIdx.x;
    const int tid = threadIdx.x;
    for (int s = tid; s < OO * HH; s += 320) wsm[s / HH][s % HH] = fcw[s];
    if (tid < OO) bsm[tid] = fcb[tid];
    __syncthreads();

    const int o = tid >> 6;
    const int b = tid & 63;
    const float* hp = g_hsT + (size_t)t * (HH * BB) + b;
    float acc = bsm[o];
    #pragma unroll 8
    for (int k = 0; k < HH; k++)
        acc = fmaf(__ldcs(hp + (size_t)k * BB), wsm[o][k], acc);
    out[(size_t)t * (BB * OO) + b * OO + o] = acc;
}

// ============================================================================
extern "C" void kernel_launch(void* const* d_in, const int* in_sizes, int n_in,
                              void* d_out, int out_size) {
    const float* x   = (const float*)d_in[0];
    const float* Wih = (const float*)d_in[1];
    const float* Whh = (const float*)d_in[2];
    const float* bih = (const float*)d_in[3];
    const float* bhh = (const float*)d_in[4];
    const float* fcw = (const float*)d_in[5];
    const float* fcb = (const float*)d_in[6];
    float* out = (float*)d_out;

    cudaFuncSetAttribute(lstm_rec_kernel,
                         cudaFuncAttributeMaxDynamicSharedMemorySize,
                         REC_SMEM_BYTES);

    pregemm_kernel<<<TT * 32, 256>>>(x, Wih, bih, bhh);
    lstm_rec_kernel<<<REC_CTAS, 256, REC_SMEM_BYTES>>>(Whh, out, out_size);
    fc_kernel<<<TT, 320>>>(fcw, fcb, out);
}

// round 5
// speedup vs baseline: 1.8629x; 1.3995x over previous
#include <cuda_runtime.h>
#include <math.h>
#include <stdint.h>

// LSTM: T=1024, B=64, I=256, H=512, O=5
// out = [outputs (T*B*O) | h_T (B*H) | c_T (B*H)]

#define TT 1024
#define BB 64
#define II 256
#define HH 512
#define G4 2048
#define OO 5

#define REC_CTAS 128
#define REC_THREADS 512

// ---- device scratch ----
__device__ float g_xgT[(size_t)TT * G4 * BB];   // [T][4H][B]
__device__ float g_hsT[(size_t)TT * HH * BB];   // [T][H][B]
__device__ float g_hT[2][HH * BB];              // ping-pong h, [512][64]
__device__ unsigned g_bar_count;
__device__ volatile unsigned g_bar_gen;

__device__ __forceinline__ float sigf(float x) {
    return 1.0f / (1.0f + __expf(-x));
}

// Packed fp32x2 FMA (sm_100+): d = a*b + d lanewise.
#define FMA2(d, a, b) \
    asm("fma.rn.f32x2 %0, %1, %2, %0;" : "+l"(d) : "l"(a), "l"(b))

__device__ __forceinline__ void cpa16(uint32_t saddr, const void* gptr) {
    asm volatile("cp.async.cg.shared.global [%0], [%1], 16;"
                 :: "r"(saddr), "l"(gptr));
}
#define CP_COMMIT() asm volatile("cp.async.commit_group;")
#define CP_WAIT(n)  asm volatile("cp.async.wait_group %0;" :: "n"(n))

// Grid-wide barrier; all 128 CTAs co-resident (1 CTA/SM @ this smem).
__device__ __forceinline__ void grid_sync() {
    __syncthreads();
    if (threadIdx.x == 0) {
        unsigned old = g_bar_gen;
        __threadfence();
        unsigned t = atomicAdd(&g_bar_count, 1u);
        if (t == REC_CTAS - 1) {
            atomicExch(&g_bar_count, 0u);
            __threadfence();
            g_bar_gen = old + 1u;
        } else {
            while (g_bar_gen == old) { }
            __threadfence();
        }
    }
    __syncthreads();
}

// ============================================================================
// Kernel 1: xg[t][n][b] = sum_k x[t][b][k] * W_ih[n][k] + b_ih[n] + b_hh[n]
// ============================================================================
#define AS_STRIDE 68
#define BS_STRIDE 66

__global__ void __launch_bounds__(256) pregemm_kernel(
    const float* __restrict__ x, const float* __restrict__ Wih,
    const float* __restrict__ bih, const float* __restrict__ bhh)
{
    __shared__ float  As[16 * AS_STRIDE];
    __shared__ float2 Bs2[16 * BS_STRIDE];

    const int t   = blockIdx.x >> 5;
    const int n0  = (blockIdx.x & 31) << 6;
    const int tid = threadIdx.x;
    const int lrow = tid >> 2;
    const int kk4  = (tid & 3) << 2;
    const int bx = tid & 15;
    const int ny = tid >> 4;

    const float* Ap = x   + (size_t)(t * BB) * II;
    const float* Bp = Wih + (size_t)n0 * II;

    unsigned long long acc[2][4];
    #pragma unroll
    for (int i = 0; i < 2; i++)
        #pragma unroll
        for (int j = 0; j < 4; j++) acc[i][j] = 0ull;

    for (int kc = 0; kc < II; kc += 16) {
        float4 a = *(const float4*)(Ap + (size_t)lrow * II + kc + kk4);
        float4 b = *(const float4*)(Bp + (size_t)lrow * II + kc + kk4);
        As[(kk4+0)*AS_STRIDE + lrow] = a.x;
        As[(kk4+1)*AS_STRIDE + lrow] = a.y;
        As[(kk4+2)*AS_STRIDE + lrow] = a.z;
        As[(kk4+3)*AS_STRIDE + lrow] = a.w;
        Bs2[(kk4+0)*BS_STRIDE + lrow] = make_float2(b.x, b.x);
        Bs2[(kk4+1)*BS_STRIDE + lrow] = make_float2(b.y, b.y);
        Bs2[(kk4+2)*BS_STRIDE + lrow] = make_float2(b.z, b.z);
        Bs2[(kk4+3)*BS_STRIDE + lrow] = make_float2(b.w, b.w);
        __syncthreads();
        #pragma unroll
        for (int kk = 0; kk < 16; kk++) {
            ulonglong2 av = *(const ulonglong2*)&As[kk*AS_STRIDE + bx*4];
            ulonglong2 b01 = *(const ulonglong2*)&Bs2[kk*BS_STRIDE + ny*4];
            ulonglong2 b23 = *(const ulonglong2*)&Bs2[kk*BS_STRIDE + ny*4 + 2];
            FMA2(acc[0][0], av.x, b01.x); FMA2(acc[1][0], av.y, b01.x);
            FMA2(acc[0][1], av.x, b01.y); FMA2(acc[1][1], av.y, b01.y);
            FMA2(acc[0][2], av.x, b23.x); FMA2(acc[1][2], av.y, b23.x);
            FMA2(acc[0][3], av.x, b23.y); FMA2(acc[1][3], av.y, b23.y);
        }
        __syncthreads();
    }

    float* outp = g_xgT + (size_t)t * (G4 * BB);
    #pragma unroll
    for (int j = 0; j < 4; j++) {
        int n = n0 + ny * 4 + j;
        float bias = bih[n] + bhh[n];
        float2 lo = *(float2*)&acc[0][j];
        float2 hi = *(float2*)&acc[1][j];
        float4 v = make_float4(lo.x + bias, lo.y + bias,
                               hi.x + bias, hi.y + bias);
        *(float4*)(outp + (size_t)n * BB + bx * 4) = v;
    }
}

// ============================================================================
// Kernel 2: persistent LSTM recurrence, register-tiled.
// 128 CTAs x 512 threads. CTA j owns 16 gate rows (4 hidden units).
// Thread (bq, rg, ks): gate rg (4 rows) x 4 batch x k-slice [64ks,64ks+64).
// Two-phase cp.async pipeline; K-split reduced through smem (aliases hsm).
// ============================================================================
#define HSM_FLOATS   (HH * BB)            // 32768
#define WD_FLOATS    (HH * 16 * 2)        // 16384
#define GSM_FLOATS   (16 * 64)
#define CSM_FLOATS   (4 * 64)
#define REC_SMEM_BYTES ((HSM_FLOATS + WD_FLOATS + GSM_FLOATS + CSM_FLOATS) * 4)

__global__ void __launch_bounds__(REC_THREADS, 1) lstm_rec_kernel(
    const float* __restrict__ Whh, float* __restrict__ d_out, int out_size)
{
    extern __shared__ float smem[];
    float*  hsm   = smem;                          // [512][64]
    float2* wdupT = (float2*)(smem + HSM_FLOATS);  // [k][rid] dup pairs
    float*  gsm   = smem + HSM_FLOATS + WD_FLOATS; // [16][64]
    float*  csm   = gsm + GSM_FLOATS;              // [4][64]
    float*  redf  = hsm;   // alias: [ks][gate*256+bq*16+unit*4+blane], 8192 f

    const int j   = blockIdx.x;
    const int tid = threadIdx.x;
    const int bq  = tid & 15;
    const int rg  = (tid >> 4) & 3;    // gate index
    const int ks  = tid >> 6;          // 0..7 k-slice

    const uint32_t hsm_s = (uint32_t)__cvta_generic_to_shared(hsm);

    // Build W_hh slice, transposed + duplicated: wdupT[k*16+rid] = (w,w)
    for (int s = tid; s < 16 * HH; s += REC_THREADS) {
        int rid = s >> 9;
        int k   = s & (HH - 1);
        int rr  = (rid >> 2) * HH + j * 4 + (rid & 3);
        float w = Whh[(size_t)rr * HH + k];
        wdupT[k * 16 + rid] = make_float2(w, w);
    }
    if (tid < 256) {   // reset cell state + this CTA's h0 slice
        int uu = tid >> 6, b = tid & 63;
        csm[uu * 64 + b] = 0.0f;
        g_hT[0][(j * 4 + uu) * BB + b] = 0.0f;
    }
    __threadfence();
    grid_sync();

    // combine-phase indices (2 outputs per thread)
    const int o0 = tid, o1 = tid + 512;
    const int rid0 = o0 >> 6, b0 = o0 & 63;
    const int rid1 = o1 >> 6, b1 = o1 & 63;
    const size_t xga0 = (size_t)((rid0 >> 2) * HH + j * 4 + (rid0 & 3)) * BB + b0;
    const size_t xga1 = (size_t)((rid1 >> 2) * HH + j * 4 + (rid1 & 3)) * BB + b1;
    // redbuf float index (sans ks term): gate*256 + bq*16 + unit*4 + blane
    const int base0 = (rid0 >> 2) * 256 + (b0 >> 2) * 16 + (rid0 & 3) * 4 + (b0 & 3);
    const int base1 = (rid1 >> 2) * 256 + (b1 >> 2) * 16 + (rid1 & 3) * 4 + (b1 & 3);

    int cur = 0;
    const float*  hrow  = hsm + bq * 4;
    const float2* wbase = wdupT + rg * 4;

    for (int step = 0; step < TT; step++) {
        const float* xgs = g_xgT + (size_t)step * (G4 * BB);
        float xg0 = __ldcs(xgs + xga0);
        float xg1 = __ldcs(xgs + xga1);

        const float* hsrc = g_hT[cur];

        // stage h: phase A = first 32 k of every ks-slice, phase B = rest
        #pragma unroll
        for (int r = 0; r < 8; r++) {
            int idx4 = r * 1024 + tid;
            cpa16(hsm_s + idx4 * 16, hsrc + idx4 * 4);
        }
        CP_COMMIT();
        #pragma unroll
        for (int r = 0; r < 8; r++) {
            int idx4 = r * 1024 + 512 + tid;
            cpa16(hsm_s + idx4 * 16, hsrc + idx4 * 4);
        }
        CP_COMMIT();

        unsigned long long a0=0,a1=0,a2=0,a3=0,a4=0,a5=0,a6=0,a7=0;

        #pragma unroll
        for (int ph = 0; ph < 2; ph++) {
            if (ph == 0) CP_WAIT(1); else CP_WAIT(0);
            __syncthreads();
            const int k0 = ks * 64 + ph * 32;
            #pragma unroll 8
            for (int k = k0; k < k0 + 32; k++) {
                ulonglong2 hv = *(const ulonglong2*)(hrow + k * 64);
                ulonglong2 wA = *(const ulonglong2*)(wbase + k * 16);
                ulonglong2 wB = *(const ulonglong2*)(wbase + k * 16 + 2);
                FMA2(a0, hv.x, wA.x); FMA2(a1, hv.y, wA.x);
                FMA2(a2, hv.x, wA.y); FMA2(a3, hv.y, wA.y);
                FMA2(a4, hv.x, wB.x); FMA2(a5, hv.y, wB.x);
                FMA2(a6, hv.x, wB.y); FMA2(a7, hv.y, wB.y);
            }
        }
        __syncthreads();   // everyone done reading hsm (redbuf aliases it)

        // write partials: per thread 4 float4 rows (unit 0..3, batch quad)
        {
            float4* rb = (float4*)redf + ((ks * 64 + rg * 16 + bq) << 2);
            union { unsigned long long u[2]; float4 f; } c0, c1, c2, c3;
            c0.u[0]=a0; c0.u[1]=a1;  c1.u[0]=a2; c1.u[1]=a3;
            c2.u[0]=a4; c2.u[1]=a5;  c3.u[0]=a6; c3.u[1]=a7;
            rb[0]=c0.f; rb[1]=c1.f; rb[2]=c2.f; rb[3]=c3.f;
        }
        __syncthreads();

        // combine K-split partials + xg -> gate pre-activations
        {
            float s0 = xg0, s1 = xg1;
            #pragma unroll
            for (int kk = 0; kk < 8; kk++) {
                s0 += redf[kk * 1024 + base0];   // (was kk*4096: R4 bug)
                s1 += redf[kk * 1024 + base1];
            }
            gsm[o0] = s0;
            gsm[o1] = s1;
        }
        __syncthreads();

        if (tid < 256) {   // elementwise LSTM cell
            int uu = tid >> 6, b = tid & 63;
            float ig = sigf(gsm[uu * 64 + b]);
            float fg = sigf(gsm[(4 + uu) * 64 + b]);
            float gg = tanhf(gsm[(8 + uu) * 64 + b]);
            float og = sigf(gsm[(12 + uu) * 64 + b]);
            float c  = fmaf(fg, csm[uu * 64 + b], ig * gg);
            float h  = og * tanhf(c);
            csm[uu * 64 + b] = c;
            int gu = j * 4 + uu;
            g_hT[cur ^ 1][gu * BB + b] = h;
            __stcs(&g_hsT[(size_t)step * (HH * BB) + gu * BB + b], h);
            if (step == TT - 1 && out_size >= TT * BB * OO + 2 * BB * HH) {
                d_out[TT * BB * OO + (size_t)b * HH + gu] = h;
                d_out[TT * BB * OO + BB * HH + (size_t)b * HH + gu] = c;
            }
        }
        __threadfence();
        grid_sync();
        cur ^= 1;
    }
}

// ============================================================================
// Kernel 3: outputs[t][b][o] = sum_k hsT[t][k][b] * fc_w[o][k] + fc_b[o]
// ============================================================================
__global__ void __launch_bounds__(320) fc_kernel(
    const float* __restrict__ fcw, const float* __restrict__ fcb,
    float* __restrict__ out)
{
    __shared__ float wsm[OO][HH];
    __shared__ float bsm[OO];
    const int t   = blockIdx.x;
    const int tid = threadIdx.x;
    for (int s = tid; s < OO * HH; s += 320) wsm[s / HH][s % HH] = fcw[s];
    if (tid < OO) bsm[tid] = fcb[tid];
    __syncthreads();

    const int o = tid >> 6;
    const int b = tid & 63;
    const float* hp = g_hsT + (size_t)t * (HH * BB) + b;
    float acc = bsm[o];
    #pragma unroll 8
    for (int k = 0; k < HH; k++)
        acc = fmaf(__ldcs(hp + (size_t)k * BB), wsm[o][k], acc);
    out[(size_t)t * (BB * OO) + b * OO + o] = acc;
}

// ============================================================================
extern "C" void kernel_launch(void* const* d_in, const int* in_sizes, int n_in,
                              void* d_out, int out_size) {
    const float* x   = (const float*)d_in[0];
    const float* Wih = (const float*)d_in[1];
    const float* Whh = (const float*)d_in[2];
    const float* bih = (const float*)d_in[3];
    const float* bhh = (const float*)d_in[4];
    const float* fcw = (const float*)d_in[5];
    const float* fcb = (const float*)d_in[6];
    float* out = (float*)d_out;

    cudaFuncSetAttribute(lstm_rec_kernel,
                         cudaFuncAttributeMaxDynamicSharedMemorySize,
                         REC_SMEM_BYTES);

    pregemm_kernel<<<TT * 32, 256>>>(x, Wih, bih, bhh);
    lstm_rec_kernel<<<REC_CTAS, REC_THREADS, REC_SMEM_BYTES>>>(Whh, out, out_size);
    fc_kernel<<<TT, 320>>>(fcw, fcb, out);
}

// round 6
// speedup vs baseline: 1.9489x; 1.0462x over previous
#include <cuda_runtime.h>
#include <math.h>
#include <stdint.h>

// LSTM: T=1024, B=64, I=256, H=512, O=5
// out = [outputs (T*B*O) | h_T (B*H) | c_T (B*H)]

#define TT 1024
#define BB 64
#define II 256
#define HH 512
#define G4 2048
#define OO 5

#define REC_CTAS 128
#define REC_THREADS 512

// ---- device scratch ----
__device__ float g_xgT[(size_t)TT * G4 * BB];   // [T][4H][B]
__device__ float g_hsT[(size_t)TT * HH * BB];   // [T][H][B]
__device__ float g_hT[2][HH * BB];              // ping-pong h, [512][64]
__device__ unsigned g_bar_count;
__device__ volatile unsigned g_bar_gen;

__device__ __forceinline__ float sigf(float x) {
    return 1.0f / (1.0f + __expf(-x));
}

// Packed fp32x2 FMA (sm_100+): d = a*b + d lanewise.
#define FMA2(d, a, b) \
    asm("fma.rn.f32x2 %0, %1, %2, %0;" : "+l"(d) : "l"(a), "l"(b))

__device__ __forceinline__ void cpa16(uint32_t saddr, const void* gptr) {
    asm volatile("cp.async.cg.shared.global [%0], [%1], 16;"
                 :: "r"(saddr), "l"(gptr));
}
#define CP_COMMIT() asm volatile("cp.async.commit_group;")
#define CP_WAIT(n)  asm volatile("cp.async.wait_group %0;" :: "n"(n))

// Grid-wide barrier; all 128 CTAs co-resident (1 CTA/SM @ this smem).
__device__ __forceinline__ void grid_sync() {
    __syncthreads();
    if (threadIdx.x == 0) {
        unsigned old = g_bar_gen;
        __threadfence();
        unsigned t = atomicAdd(&g_bar_count, 1u);
        if (t == REC_CTAS - 1) {
            atomicExch(&g_bar_count, 0u);
            __threadfence();
            g_bar_gen = old + 1u;
        } else {
            while (g_bar_gen == old) { }
            __threadfence();
        }
    }
    __syncthreads();
}

// ============================================================================
// Kernel 1: xg[t][n][b] = sum_k x[t][b][k] * W_ih[n][k] + b_ih[n] + b_hh[n]
// ============================================================================
#define AS_STRIDE 68
#define BS_STRIDE 66

__global__ void __launch_bounds__(256) pregemm_kernel(
    const float* __restrict__ x, const float* __restrict__ Wih,
    const float* __restrict__ bih, const float* __restrict__ bhh)
{
    __shared__ float  As[16 * AS_STRIDE];
    __shared__ float2 Bs2[16 * BS_STRIDE];

    const int t   = blockIdx.x >> 5;
    const int n0  = (blockIdx.x & 31) << 6;
    const int tid = threadIdx.x;
    const int lrow = tid >> 2;
    const int kk4  = (tid & 3) << 2;
    const int bx = tid & 15;
    const int ny = tid >> 4;

    const float* Ap = x   + (size_t)(t * BB) * II;
    const float* Bp = Wih + (size_t)n0 * II;

    unsigned long long acc[2][4];
    #pragma unroll
    for (int i = 0; i < 2; i++)
        #pragma unroll
        for (int j = 0; j < 4; j++) acc[i][j] = 0ull;

    for (int kc = 0; kc < II; kc += 16) {
        float4 a = *(const float4*)(Ap + (size_t)lrow * II + kc + kk4);
        float4 b = *(const float4*)(Bp + (size_t)lrow * II + kc + kk4);
        As[(kk4+0)*AS_STRIDE + lrow] = a.x;
        As[(kk4+1)*AS_STRIDE + lrow] = a.y;
        As[(kk4+2)*AS_STRIDE + lrow] = a.z;
        As[(kk4+3)*AS_STRIDE + lrow] = a.w;
        Bs2[(kk4+0)*BS_STRIDE + lrow] = make_float2(b.x, b.x);
        Bs2[(kk4+1)*BS_STRIDE + lrow] = make_float2(b.y, b.y);
        Bs2[(kk4+2)*BS_STRIDE + lrow] = make_float2(b.z, b.z);
        Bs2[(kk4+3)*BS_STRIDE + lrow] = make_float2(b.w, b.w);
        __syncthreads();
        #pragma unroll
        for (int kk = 0; kk < 16; kk++) {
            ulonglong2 av = *(const ulonglong2*)&As[kk*AS_STRIDE + bx*4];
            ulonglong2 b01 = *(const ulonglong2*)&Bs2[kk*BS_STRIDE + ny*4];
            ulonglong2 b23 = *(const ulonglong2*)&Bs2[kk*BS_STRIDE + ny*4 + 2];
            FMA2(acc[0][0], av.x, b01.x); FMA2(acc[1][0], av.y, b01.x);
            FMA2(acc[0][1], av.x, b01.y); FMA2(acc[1][1], av.y, b01.y);
            FMA2(acc[0][2], av.x, b23.x); FMA2(acc[1][2], av.y, b23.x);
            FMA2(acc[0][3], av.x, b23.y); FMA2(acc[1][3], av.y, b23.y);
        }
        __syncthreads();
    }

    float* outp = g_xgT + (size_t)t * (G4 * BB);
    #pragma unroll
    for (int j = 0; j < 4; j++) {
        int n = n0 + ny * 4 + j;
        float bias = bih[n] + bhh[n];
        float2 lo = *(float2*)&acc[0][j];
        float2 hi = *(float2*)&acc[1][j];
        float4 v = make_float4(lo.x + bias, lo.y + bias,
                               hi.x + bias, hi.y + bias);
        *(float4*)(outp + (size_t)n * BB + bx * 4) = v;
    }
}

// ============================================================================
// Kernel 2: persistent LSTM recurrence, register-tiled.
// 128 CTAs x 512 threads. CTA j owns 16 gate rows (4 hidden units).
// Thread (bq, rg, ks): gate rg (4 rows) x 4 batch x k-slice [64ks,64ks+64).
// Two-phase cp.async pipeline; K-split reduced through smem (aliases hsm).
// ============================================================================
#define HSM_FLOATS   (HH * BB)            // 32768
#define WD_FLOATS    (HH * 16 * 2)        // 16384
#define GSM_FLOATS   (16 * 64)
#define CSM_FLOATS   (4 * 64)
#define REC_SMEM_BYTES ((HSM_FLOATS + WD_FLOATS + GSM_FLOATS + CSM_FLOATS) * 4)

__global__ void __launch_bounds__(REC_THREADS, 1) lstm_rec_kernel(
    const float* __restrict__ Whh, float* __restrict__ d_out, int out_size)
{
    extern __shared__ float smem[];
    float*  hsm   = smem;                          // [512][64]
    float2* wdupT = (float2*)(smem + HSM_FLOATS);  // [k][rid] dup pairs
    float*  gsm   = smem + HSM_FLOATS + WD_FLOATS; // [16][64]
    float*  csm   = gsm + GSM_FLOATS;              // [4][64]
    float*  redf  = hsm;   // alias: [ks][gate*256+bq*16+unit*4+blane], 8192 f

    const int j   = blockIdx.x;
    const int tid = threadIdx.x;
    const int bq  = tid & 15;
    const int rg  = (tid >> 4) & 3;    // gate index
    const int ks  = tid >> 6;          // 0..7 k-slice

    const uint32_t hsm_s = (uint32_t)__cvta_generic_to_shared(hsm);

    // Build W_hh slice, transposed + duplicated: wdupT[k*16+rid] = (w,w)
    for (int s = tid; s < 16 * HH; s += REC_THREADS) {
        int rid = s >> 9;
        int k   = s & (HH - 1);
        int rr  = (rid >> 2) * HH + j * 4 + (rid & 3);
        float w = Whh[(size_t)rr * HH + k];
        wdupT[k * 16 + rid] = make_float2(w, w);
    }
    if (tid < 256) {   // reset cell state + this CTA's h0 slice
        int uu = tid >> 6, b = tid & 63;
        csm[uu * 64 + b] = 0.0f;
        g_hT[0][(j * 4 + uu) * BB + b] = 0.0f;
    }
    __threadfence();
    grid_sync();

    // combine-phase indices (2 outputs per thread)
    const int o0 = tid, o1 = tid + 512;
    const int rid0 = o0 >> 6, b0 = o0 & 63;
    const int rid1 = o1 >> 6, b1 = o1 & 63;
    const size_t xga0 = (size_t)((rid0 >> 2) * HH + j * 4 + (rid0 & 3)) * BB + b0;
    const size_t xga1 = (size_t)((rid1 >> 2) * HH + j * 4 + (rid1 & 3)) * BB + b1;
    // redbuf float index (sans ks term): gate*256 + bq*16 + unit*4 + blane
    const int base0 = (rid0 >> 2) * 256 + (b0 >> 2) * 16 + (rid0 & 3) * 4 + (b0 & 3);
    const int base1 = (rid1 >> 2) * 256 + (b1 >> 2) * 16 + (rid1 & 3) * 4 + (b1 & 3);

    int cur = 0;
    const float*  hrow  = hsm + bq * 4;
    const float2* wbase = wdupT + rg * 4;

    for (int step = 0; step < TT; step++) {
        const float* xgs = g_xgT + (size_t)step * (G4 * BB);
        float xg0 = __ldcs(xgs + xga0);
        float xg1 = __ldcs(xgs + xga1);

        const float* hsrc = g_hT[cur];

        // stage h: phase A = first 32 k of every ks-slice, phase B = rest
        #pragma unroll
        for (int r = 0; r < 8; r++) {
            int idx4 = r * 1024 + tid;
            cpa16(hsm_s + idx4 * 16, hsrc + idx4 * 4);
        }
        CP_COMMIT();
        #pragma unroll
        for (int r = 0; r < 8; r++) {
            int idx4 = r * 1024 + 512 + tid;
            cpa16(hsm_s + idx4 * 16, hsrc + idx4 * 4);
        }
        CP_COMMIT();

        unsigned long long a0=0,a1=0,a2=0,a3=0,a4=0,a5=0,a6=0,a7=0;

        #pragma unroll
        for (int ph = 0; ph < 2; ph++) {
            if (ph == 0) CP_WAIT(1); else CP_WAIT(0);
            __syncthreads();
            const int k0 = ks * 64 + ph * 32;
            #pragma unroll 8
            for (int k = k0; k < k0 + 32; k++) {
                ulonglong2 hv = *(const ulonglong2*)(hrow + k * 64);
                ulonglong2 wA = *(const ulonglong2*)(wbase + k * 16);
                ulonglong2 wB = *(const ulonglong2*)(wbase + k * 16 + 2);
                FMA2(a0, hv.x, wA.x); FMA2(a1, hv.y, wA.x);
                FMA2(a2, hv.x, wA.y); FMA2(a3, hv.y, wA.y);
                FMA2(a4, hv.x, wB.x); FMA2(a5, hv.y, wB.x);
                FMA2(a6, hv.x, wB.y); FMA2(a7, hv.y, wB.y);
            }
        }
        __syncthreads();   // everyone done reading hsm (redbuf aliases it)

        // write partials: per thread 4 float4 rows (unit 0..3, batch quad)
        {
            float4* rb = (float4*)redf + ((ks * 64 + rg * 16 + bq) << 2);
            union { unsigned long long u[2]; float4 f; } c0, c1, c2, c3;
            c0.u[0]=a0; c0.u[1]=a1;  c1.u[0]=a2; c1.u[1]=a3;
            c2.u[0]=a4; c2.u[1]=a5;  c3.u[0]=a6; c3.u[1]=a7;
            rb[0]=c0.f; rb[1]=c1.f; rb[2]=c2.f; rb[3]=c3.f;
        }
        __syncthreads();

        // combine K-split partials + xg -> gate pre-activations
        {
            float s0 = xg0, s1 = xg1;
            #pragma unroll
            for (int kk = 0; kk < 8; kk++) {
                s0 += redf[kk * 1024 + base0];   // (was kk*4096: R4 bug)
                s1 += redf[kk * 1024 + base1];
            }
            gsm[o0] = s0;
            gsm[o1] = s1;
        }
        __syncthreads();

        if (tid < 256) {   // elementwise LSTM cell
            int uu = tid >> 6, b = tid & 63;
            float ig = sigf(gsm[uu * 64 + b]);
            float fg = sigf(gsm[(4 + uu) * 64 + b]);
            float gg = tanhf(gsm[(8 + uu) * 64 + b]);
            float og = sigf(gsm[(12 + uu) * 64 + b]);
            float c  = fmaf(fg, csm[uu * 64 + b], ig * gg);
            float h  = og * tanhf(c);
            csm[uu * 64 + b] = c;
            int gu = j * 4 + uu;
            g_hT[cur ^ 1][gu * BB + b] = h;
            __stcs(&g_hsT[(size_t)step * (HH * BB) + gu * BB + b], h);
            if (step == TT - 1 && out_size >= TT * BB * OO + 2 * BB * HH) {
                d_out[TT * BB * OO + (size_t)b * HH + gu] = h;
                d_out[TT * BB * OO + BB * HH + (size_t)b * HH + gu] = c;
            }
        }
        __threadfence();
        grid_sync();
        cur ^= 1;
    }
}

// ============================================================================
// Kernel 3: outputs[t][b][o] = sum_k hsT[t][k][b] * fc_w[o][k] + fc_b[o]
// ============================================================================
__global__ void __launch_bounds__(320) fc_kernel(
    const float* __restrict__ fcw, const float* __restrict__ fcb,
    float* __restrict__ out)
{
    __shared__ float wsm[OO][HH];
    __shared__ float bsm[OO];
    const int t   = blockIdx.x;
    const int tid = threadIdx.x;
    for (int s = tid; s < OO * HH; s += 320) wsm[s / HH][s % HH] = fcw[s];
    if (tid < OO) bsm[tid] = fcb[tid];
    __syncthreads();

    const int o = tid >> 6;
    const int b = tid & 63;
    const float* hp = g_hsT + (size_t)t * (HH * BB) + b;
    float acc = bsm[o];
    #pragma unroll 8
    for (int k = 0; k < HH; k++)
        acc = fmaf(__ldcs(hp + (size_t)k * BB), wsm[o][k], acc);
    out[(size_t)t * (BB * OO) + b * OO + o] = acc;
}

// ============================================================================
extern "C" void kernel_launch(void* const* d_in, const int* in_sizes, int n_in,
                              void* d_out, int out_size) {
    const float* x   = (const float*)d_in[0];
    const float* Wih = (const float*)d_in[1];
    const float* Whh = (const float*)d_in[2];
    const float* bih = (const float*)d_in[3];
    const float* bhh = (const float*)d_in[4];
    const float* fcw = (const float*)d_in[5];
    const float* fcb = (const float*)d_in[6];
    float* out = (float*)d_out;

    cudaFuncSetAttribute(lstm_rec_kernel,
                         cudaFuncAttributeMaxDynamicSharedMemorySize,
                         REC_SMEM_BYTES);

    pregemm_kernel<<<TT * 32, 256>>>(x, Wih, bih, bhh);
    lstm_rec_kernel<<<REC_CTAS, REC_THREADS, REC_SMEM_BYTES>>>(Whh, out, out_size);
    fc_kernel<<<TT, 320>>>(fcw, fcb, out);
}

// round 8
// speedup vs baseline: 2.4473x; 1.2558x over previous
#include <cuda_runtime.h>
#include <cuda_bf16.h>
#include <math.h>
#include <stdint.h>

// LSTM: T=1024, B=64, I=256, H=512, O=5
// out = [outputs (T*B*O) | h_T (B*H) | c_T (B*H)]

#define TT 1024
#define BB 64
#define II 256
#define HH 512
#define G4 2048
#define OO 5
#define REC_CTAS 128

// ---- device scratch ----
__device__ float g_xgT[(size_t)TT * G4 * BB];     // [T][4H][B]
__device__ float g_hsT[(size_t)TT * HH * BB];     // [T][H][B]
// Whh split-bf16 per CTA tile: [(m*2+copy)*16 + r][512], r = gate*4+u
__device__ __nv_bfloat16 g_Abf[128 * 2 * 16 * 512];
// h split-bf16, ping-pong: [pp 2][copy 2][k 512][b 64]
__device__ __nv_bfloat16 g_hbf[2 * 2 * 512 * 64];
__device__ unsigned g_bar_count;
__device__ volatile unsigned g_bar_gen;

__device__ __forceinline__ float sigf(float x) {
    return 1.0f / (1.0f + __expf(-x));
}
#define FMA2(d, a, b) \
    asm("fma.rn.f32x2 %0, %1, %2, %0;" : "+l"(d) : "l"(a), "l"(b))

__device__ __forceinline__ void cpa16(uint32_t saddr, const void* gptr) {
    asm volatile("cp.async.cg.shared.global [%0], [%1], 16;"
                 :: "r"(saddr), "l"(gptr));
}
#define CP_COMMIT() asm volatile("cp.async.commit_group;")
#define CP_WAIT(n)  asm volatile("cp.async.wait_group %0;" :: "n"(n))

#define LDSM_X4(r0,r1,r2,r3,addr) \
    asm volatile("ldmatrix.sync.aligned.m8n8.x4.shared.b16 {%0,%1,%2,%3}, [%4];" \
        : "=r"(r0),"=r"(r1),"=r"(r2),"=r"(r3) : "r"(addr))
#define LDSM_X2T(r0,r1,addr) \
    asm volatile("ldmatrix.sync.aligned.m8n8.x2.trans.shared.b16 {%0,%1}, [%2];" \
        : "=r"(r0),"=r"(r1) : "r"(addr))
#define MMA16816(d0,d1,d2,d3,a0,a1,a2,a3,b0,b1) \
    asm volatile("mma.sync.aligned.m16n8k16.row.col.f32.bf16.bf16.f32 " \
        "{%0,%1,%2,%3}, {%4,%5,%6,%7}, {%8,%9}, {%0,%1,%2,%3};" \
        : "+f"(d0),"+f"(d1),"+f"(d2),"+f"(d3) \
        : "r"(a0),"r"(a1),"r"(a2),"r"(a3),"r"(b0),"r"(b1))

// Grid barrier; 128 CTAs co-resident (1/SM forced by smem)
__device__ __forceinline__ void grid_sync() {
    __syncthreads();
    if (threadIdx.x == 0) {
        unsigned old = g_bar_gen;
        __threadfence();
        unsigned t = atomicAdd(&g_bar_count, 1u);
        if (t == REC_CTAS - 1) {
            atomicExch(&g_bar_count, 0u);
            __threadfence();
            g_bar_gen = old + 1u;
        } else {
            while (g_bar_gen == old) { }
            __threadfence();
        }
    }
    __syncthreads();
}

// ============================================================================
// Kernel 0: Whh -> split-bf16 CTA tiles. R = gate*512 + m*4 + u.
// ============================================================================
__global__ void prep_whh(const float* __restrict__ Whh) {
    int R = blockIdx.x;
    int gate = R >> 9, rem = R & 511;
    int m = rem >> 2, u = rem & 3;
    int r = gate * 4 + u;
    for (int k = threadIdx.x; k < HH; k += blockDim.x) {
        float w = Whh[(size_t)R * HH + k];
        __nv_bfloat16 hi = __float2bfloat16(w);
        __nv_bfloat16 lo = __float2bfloat16(w - __bfloat162float(hi));
        g_Abf[((size_t)(m * 2 + 0) * 16 + r) * HH + k] = hi;
        g_Abf[((size_t)(m * 2 + 1) * 16 + r) * HH + k] = lo;
    }
}

// ============================================================================
// Kernel 1: xg pre-GEMM (unchanged f32x2 SIMT)
// ============================================================================
#define AS_STRIDE 68
#define BS_STRIDE 66

__global__ void __launch_bounds__(256) pregemm_kernel(
    const float* __restrict__ x, const float* __restrict__ Wih,
    const float* __restrict__ bih, const float* __restrict__ bhh)
{
    __shared__ float  As[16 * AS_STRIDE];
    __shared__ float2 Bs2[16 * BS_STRIDE];
    const int t = blockIdx.x >> 5, n0 = (blockIdx.x & 31) << 6;
    const int tid = threadIdx.x;
    const int lrow = tid >> 2, kk4 = (tid & 3) << 2;
    const int bx = tid & 15, ny = tid >> 4;
    const float* Ap = x + (size_t)(t * BB) * II;
    const float* Bp = Wih + (size_t)n0 * II;

    unsigned long long acc[2][4];
    #pragma unroll
    for (int i = 0; i < 2; i++)
        #pragma unroll
        for (int j = 0; j < 4; j++) acc[i][j] = 0ull;

    for (int kc = 0; kc < II; kc += 16) {
        float4 a = *(const float4*)(Ap + (size_t)lrow * II + kc + kk4);
        float4 b = *(const float4*)(Bp + (size_t)lrow * II + kc + kk4);
        As[(kk4+0)*AS_STRIDE + lrow] = a.x;
        As[(kk4+1)*AS_STRIDE + lrow] = a.y;
        As[(kk4+2)*AS_STRIDE + lrow] = a.z;
        As[(kk4+3)*AS_STRIDE + lrow] = a.w;
        Bs2[(kk4+0)*BS_STRIDE + lrow] = make_float2(b.x, b.x);
        Bs2[(kk4+1)*BS_STRIDE + lrow] = make_float2(b.y, b.y);
        Bs2[(kk4+2)*BS_STRIDE + lrow] = make_float2(b.z, b.z);
        Bs2[(kk4+3)*BS_STRIDE + lrow] = make_float2(b.w, b.w);
        __syncthreads();
        #pragma unroll
        for (int kk = 0; kk < 16; kk++) {
            ulonglong2 av  = *(const ulonglong2*)&As[kk*AS_STRIDE + bx*4];
            ulonglong2 b01 = *(const ulonglong2*)&Bs2[kk*BS_STRIDE + ny*4];
            ulonglong2 b23 = *(const ulonglong2*)&Bs2[kk*BS_STRIDE + ny*4 + 2];
            FMA2(acc[0][0], av.x, b01.x); FMA2(acc[1][0], av.y, b01.x);
            FMA2(acc[0][1], av.x, b01.y); FMA2(acc[1][1], av.y, b01.y);
            FMA2(acc[0][2], av.x, b23.x); FMA2(acc[1][2], av.y, b23.x);
            FMA2(acc[0][3], av.x, b23.y); FMA2(acc[1][3], av.y, b23.y);
        }
        __syncthreads();
    }
    float* outp = g_xgT + (size_t)t * (G4 * BB);
    #pragma unroll
    for (int j = 0; j < 4; j++) {
        int n = n0 + ny * 4 + j;
        float bias = bih[n] + bhh[n];
        float2 lo = *(float2*)&acc[0][j];
        float2 hi = *(float2*)&acc[1][j];
        *(float4*)(outp + (size_t)n * BB + bx * 4) =
            make_float4(lo.x + bias, lo.y + bias, hi.x + bias, hi.y + bias);
    }
}

// ============================================================================
// Kernel 2: persistent HMMA recurrence. 128 CTAs x 256 threads (8 warps).
// CTA m: D[16 rows = 4 gates x 4 units][64 batch] = 3-term split-bf16 MMA.
// Warp w: N-slice [8w, 8w+8). A resident in smem; h staged per step.
// smem layout (bytes from aligned base):
//   hsm  [copy 2][k 512][72 bf16]  0      .. 147456   (row stride 144B)
//   Asm  [copy 2][r 16][520 bf16]  147456 .. 180736   (row stride 1040B)
//   gsm  [16][66 f32]              180736 .. 184960
//   csm  [4*64 f32]                184960 .. 185984
// ============================================================================
#define HSM_OFF   0
#define HSM_COPY  73728
#define ASM_OFF   147456
#define ASM_COPY  16640
#define GSM_OFF   180736
#define GSM_STR   66
#define CSM_OFF   184960
#define REC_SMEM  (185984 + 1024)

__global__ void __launch_bounds__(256, 1) lstm_rec_mma(
    float* __restrict__ d_out, int out_size)
{
    extern __shared__ char smraw[];
    uint32_t sb0 = (uint32_t)__cvta_generic_to_shared(smraw);
    uint32_t sb  = (sb0 + 127u) & ~127u;
    char* smem = smraw + (sb - sb0);

    float* gsm = (float*)(smem + GSM_OFF);
    float* csm = (float*)(smem + CSM_OFF);

    const int m    = blockIdx.x;
    const int tid  = threadIdx.x;
    const int wid  = tid >> 5;
    const int lane = tid & 31;
    const int b    = tid & 63;       // cell-phase batch
    const int u    = tid >> 6;       // cell-phase unit 0..3

    // ---- one-time init ----
    // A tiles -> smem (both copies), 16B chunks
    for (int idx = tid; idx < 2 * 16 * 64; idx += 256) {
        int c = idx >> 10, rem = idx & 1023;
        int r = rem >> 6, i = rem & 63;
        uint4 v = *(const uint4*)(g_Abf + ((size_t)(m*2+c)*16 + r) * HH + i*8);
        *(uint4*)(smem + ASM_OFF + c*ASM_COPY + r*1040 + i*16) = v;
    }
    // zero h ping-pong (global, shared across CTAs) + cell state
    for (int i = m * 256 + tid; i < (2*2*512*64)/8; i += REC_CTAS * 256)
        ((uint4*)g_hbf)[i] = make_uint4(0, 0, 0, 0);
    csm[u * 64 + b] = 0.0f;
    __threadfence();
    grid_sync();

    // ldmatrix base addresses
    const uint32_t aBase = sb + ASM_OFF + (uint32_t)(lane & 15) * 1040
                         + (uint32_t)(lane >> 4) * 16;
    const uint32_t bBase = sb + HSM_OFF + (uint32_t)(lane & 15) * 144
                         + (uint32_t)wid * 16;
    const uint32_t hsm_s = sb + HSM_OFF;

    int cur = 0;
    for (int step = 0; step < TT; step++) {
        const __nv_bfloat16* hsrc = g_hbf + (size_t)(cur * 2) * (512 * 64);

        // stage h hi/lo in 2 phases (k<256, k>=256), 16 cp.async each
        #pragma unroll
        for (int p = 0; p < 2; p++) {
            #pragma unroll
            for (int jj = 0; jj < 8; jj++) {
                int ch = jj * 256 + tid;           // 0..2047
                int k  = p * 256 + (ch >> 3);
                int i  = ch & 7;
                #pragma unroll
                for (int c = 0; c < 2; c++)
                    cpa16(hsm_s + c*HSM_COPY + k*144 + i*16,
                          hsrc + c*(512*64) + k*64 + i*8);
            }
            CP_COMMIT();
        }

        // prefetch xg for the cell phase
        const float* xgs = g_xgT + (size_t)step * (G4 * BB);
        int gu = m * 4 + u;
        float xg0 = __ldcs(xgs + (size_t)(0*HH + gu) * BB + b);
        float xg1 = __ldcs(xgs + (size_t)(1*HH + gu) * BB + b);
        float xg2 = __ldcs(xgs + (size_t)(2*HH + gu) * BB + b);
        float xg3 = __ldcs(xgs + (size_t)(3*HH + gu) * BB + b);

        float d0 = 0.f, d1 = 0.f, d2 = 0.f, d3 = 0.f;

        #pragma unroll
        for (int p = 0; p < 2; p++) {
            if (p == 0) CP_WAIT(1); else CP_WAIT(0);
            __syncthreads();
            #pragma unroll 4
            for (int ks = p * 16; ks < p * 16 + 16; ks++) {
                uint32_t ah0,ah1,ah2,ah3, al0,al1,al2,al3;
                uint32_t bh0,bh1, bl0,bl1;
                LDSM_X4(ah0,ah1,ah2,ah3, aBase + ks*32);
                LDSM_X4(al0,al1,al2,al3, aBase + ASM_COPY + ks*32);
                LDSM_X2T(bh0,bh1, bBase + ks*2304);
                LDSM_X2T(bl0,bl1, bBase + HSM_COPY + ks*2304);
                MMA16816(d0,d1,d2,d3, ah0,ah1,ah2,ah3, bh0,bh1);
                MMA16816(d0,d1,d2,d3, ah0,ah1,ah2,ah3, bl0,bl1);
                MMA16816(d0,d1,d2,d3, al0,al1,al2,al3, bh0,bh1);
            }
        }

        // epilogue: D fragments -> gsm[row][b]
        {
            int r0 = lane >> 2;
            int cB = wid * 8 + (lane & 3) * 2;
            *(float2*)&gsm[r0 * GSM_STR + cB]       = make_float2(d0, d1);
            *(float2*)&gsm[(r0 + 8) * GSM_STR + cB] = make_float2(d2, d3);
        }
        __syncthreads();

        // cell update: thread (u, b); rows r = gate*4 + u
        {
            float p0 = gsm[(0*4 + u) * GSM_STR + b] + xg0;
            float p1 = gsm[(1*4 + u) * GSM_STR + b] + xg1;
            float p2 = gsm[(2*4 + u) * GSM_STR + b] + xg2;
            float p3 = gsm[(3*4 + u) * GSM_STR + b] + xg3;
            float ig = sigf(p0), fg = sigf(p1);
            float gg = tanhf(p2), og = sigf(p3);
            float c  = fmaf(fg, csm[u * 64 + b], ig * gg);
            float h  = og * tanhf(c);
            csm[u * 64 + b] = c;
            __stcs(&g_hsT[(size_t)step * (HH*BB) + (size_t)gu * BB + b], h);
            __nv_bfloat16 hh = __float2bfloat16(h);
            __nv_bfloat16 hl = __float2bfloat16(h - __bfloat162float(hh));
            int nxt = cur ^ 1;
            g_hbf[((size_t)(nxt*2 + 0) * 512 + gu) * 64 + b] = hh;
            g_hbf[((size_t)(nxt*2 + 1) * 512 + gu) * 64 + b] = hl;
            if (step == TT - 1 && out_size >= TT*BB*OO + 2*BB*HH) {
                d_out[TT*BB*OO + (size_t)b * HH + gu] = h;
                d_out[TT*BB*OO + BB*HH + (size_t)b * HH + gu] = c;
            }
        }
        __threadfence();
        grid_sync();
        cur ^= 1;
    }
}

// ============================================================================
// Kernel 3: FC epilogue
// ============================================================================
__global__ void __launch_bounds__(320) fc_kernel(
    const float* __restrict__ fcw, const float* __restrict__ fcb,
    float* __restrict__ out)
{
    __shared__ float wsm[OO][HH];
    __shared__ float bsm[OO];
    const int t = blockIdx.x, tid = threadIdx.x;
    for (int s = tid; s < OO * HH; s += 320) wsm[s / HH][s % HH] = fcw[s];
    if (tid < OO) bsm[tid] = fcb[tid];
    __syncthreads();
    const int o = tid >> 6, b = tid & 63;
    const float* hp = g_hsT + (size_t)t * (HH * BB) + b;
    float acc = bsm[o];
    #pragma unroll 8
    for (int k = 0; k < HH; k++)
        acc = fmaf(__ldcs(hp + (size_t)k * BB), wsm[o][k], acc);
    out[(size_t)t * (BB * OO) + b * OO + o] = acc;
}

// ============================================================================
extern "C" void kernel_launch(void* const* d_in, const int* in_sizes, int n_in,
                              void* d_out, int out_size) {
    const float* x   = (const float*)d_in[0];
    const float* Wih = (const float*)d_in[1];
    const float* Whh = (const float*)d_in[2];
    const float* bih = (const float*)d_in[3];
    const float* bhh = (const float*)d_in[4];
    const float* fcw = (const float*)d_in[5];
    const float* fcb = (const float*)d_in[6];
    float* out = (float*)d_out;

    cudaFuncSetAttribute(lstm_rec_mma,
                         cudaFuncAttributeMaxDynamicSharedMemorySize, REC_SMEM);

    prep_whh<<<G4, 128>>>(Whh);
    pregemm_kernel<<<TT * 32, 256>>>(x, Wih, bih, bhh);
    lstm_rec_mma<<<REC_CTAS, 256, REC_SMEM>>>(out, out_size);
    fc_kernel<<<TT, 320>>>(fcw, fcb, out);
}